// round 8
// baseline (speedup 1.0000x reference)
#include <cuda_runtime.h>
#include <cuda_bf16.h>
#include <math.h>
#include <stdint.h>

// Laplace diagonal recurrence:
//   out[t, i, f] = e[i] * out[t-1, i, f] + decay[i] * inp[t, f]
// T = 2048, N_S = 108, F = 256, fp32.
//
// R8: stores moved off the warps. Each block computes 12 i-values for a
// 128-t chunk (warm-up 64), writes each output row into a smem tile
// (12 i x 256 f = 12KB contiguous), and pushes it to GMEM with
// cp.async.bulk (async proxy, bulk_group). Double-buffered 4-row tiles,
// wait_group.read recycling. Input via 2-tile-ahead register prefetch.
// Grid = 9 x 16 = 144 blocks (1/SM), 256 threads.

constexpr int T_LEN  = 2048;
constexpr int F      = 256;
constexpr int NS     = 108;
constexpr int CHUNK  = 128;
constexpr int WARM   = 64;
constexpr int NCHUNK = T_LEN / CHUNK;    // 16
constexpr int GI     = 12;               // i per block
constexpr int NIB    = NS / GI;          // 9
constexpr int F4     = F / 4;            // 64
constexpr int RT     = 4;                // rows per output tile
constexpr int THR    = 256;
constexpr int ROW_BYTES  = GI * F * 4;   // 12288
constexpr int TILE_F4    = RT * GI * F4; // 3072 float4 per tile buffer
constexpr int SMEM_BYTES = 2 * TILE_F4 * 16;  // 98304

typedef unsigned long long u64;
typedef unsigned int       u32;

__device__ __forceinline__ u64 fma2(u64 a, u64 b, u64 c) {
    u64 d;
    asm("fma.rn.f32x2 %0, %1, %2, %3;" : "=l"(d) : "l"(a), "l"(b), "l"(c));
    return d;
}
__device__ __forceinline__ u64 mul2(u64 a, u64 b) {
    u64 d;
    asm("mul.rn.f32x2 %0, %1, %2;" : "=l"(d) : "l"(a), "l"(b));
    return d;
}
__device__ __forceinline__ u64 pack2(float lo, float hi) {
    u64 d;
    asm("mov.b64 %0, {%1, %2};" : "=l"(d) : "f"(lo), "f"(hi));
    return d;
}

union V4 {
    float4 f;
    u64    u[2];
};

__device__ __forceinline__ void bulk_store(const void* gdst, const void* ssrc, u32 bytes) {
    u32 sa = (u32)__cvta_generic_to_shared(ssrc);
    asm volatile("cp.async.bulk.global.shared::cta.bulk_group [%0], [%1], %2;"
                 :: "l"(gdst), "r"(sa), "r"(bytes) : "memory");
}
__device__ __forceinline__ void bulk_commit() {
    asm volatile("cp.async.bulk.commit_group;" ::: "memory");
}
__device__ __forceinline__ void bulk_wait_read1() {
    asm volatile("cp.async.bulk.wait_group.read 1;" ::: "memory");
}
__device__ __forceinline__ void bulk_wait_all() {
    asm volatile("cp.async.bulk.wait_group 0;" ::: "memory");
}
__device__ __forceinline__ void fence_async() {
    asm volatile("fence.proxy.async;" ::: "memory");
}

__global__ __launch_bounds__(THR)
void laplace_kernel(const float* __restrict__ inp, float* __restrict__ out) {
    extern __shared__ float4 sbuf[];   // [2][RT][GI][F4]

    const int tid = threadIdx.x;
    const int fq  = tid & 63;          // float4 lane
    const int iq  = tid >> 6;          // 0..3 -> 3 i each
    const int ib  = blockIdx.x;        // 0..8
    const int chunk = blockIdx.y;      // 0..15

    // Per-i constants (double precision; matches reference ~1e-7).
    u64 e2[3], d2[3];
    const double c = pow(20.0, 1.0 / 99.0) - 1.0;
    #pragma unroll
    for (int k = 0; k < 3; k++) {
        int i = ib * GI + iq * 3 + k;
        double tau = pow(1.0 + c, (double)(i - 4));
        double s   = 4.0 / tau;
        double ed  = exp(-s);
        float ef = (float)ed;
        float df = (float)((1.0 - ed) / s);
        e2[k] = pack2(ef, ef);
        d2[k] = pack2(df, df);
    }

    const int t_start = chunk * CHUNK;
    const int warm    = (t_start < WARM) ? t_start : WARM;   // 0 or 64
    const int t0      = t_start - warm;
    const int steps   = warm + CHUNK;                         // 128 or 192
    const int ntiles  = steps / RT;                           // 32 or 48
    const int stile0  = warm / RT;                            // 0 or 16

    const float4* __restrict__ gx = reinterpret_cast<const float4*>(inp)
                                    + (size_t)t0 * F4 + fq;

    // Scaled states: st' = e*st' + x;  out = dcy*st'.
    u64 st[3][2];
    #pragma unroll
    for (int k = 0; k < 3; k++) { st[k][0] = 0ull; st[k][1] = 0ull; }

    // x prefetch: 3 tile-buffers of 4 rows, loaded 2 tiles ahead.
    V4 xb[3][RT];
    #pragma unroll
    for (int s = 0; s < 2; s++)
        #pragma unroll
        for (int j = 0; j < RT; j++)
            xb[s][j].f = __ldg(gx + (size_t)(s * RT + j) * F4);

    const char* gout_base = reinterpret_cast<const char*>(out);
    const size_t i_off = (size_t)(ib * GI) * 1024;   // byte offset of i-block in a row

    int s = 0;
    // ---- warm tiles (no stores) ----
    for (; s < stile0; s++) {
        const int pre = s + 2;
        if (pre < ntiles) {
            #pragma unroll
            for (int j = 0; j < RT; j++)
                xb[pre % 3][j].f = __ldg(gx + (size_t)(pre * RT + j) * F4);
        }
        #pragma unroll
        for (int j = 0; j < RT; j++) {
            V4 x = xb[s % 3][j];
            #pragma unroll
            for (int k = 0; k < 3; k++) {
                st[k][0] = fma2(e2[k], st[k][0], x.u[0]);
                st[k][1] = fma2(e2[k], st[k][1], x.u[1]);
            }
        }
    }

    // ---- storing tiles ----
    for (int ot = 0; s < ntiles; s++, ot++) {
        if (tid == 0 && ot >= 2) bulk_wait_read1();   // recycle buf[ot&1]
        __syncthreads();

        const int pre = s + 2;
        if (pre < ntiles) {
            #pragma unroll
            for (int j = 0; j < RT; j++)
                xb[pre % 3][j].f = __ldg(gx + (size_t)(pre * RT + j) * F4);
        }

        float4* buf = &sbuf[(ot & 1) * TILE_F4];
        #pragma unroll
        for (int j = 0; j < RT; j++) {
            V4 x = xb[s % 3][j];
            #pragma unroll
            for (int k = 0; k < 3; k++) {
                st[k][0] = fma2(e2[k], st[k][0], x.u[0]);
                st[k][1] = fma2(e2[k], st[k][1], x.u[1]);
                V4 o;
                o.u[0] = mul2(d2[k], st[k][0]);
                o.u[1] = mul2(d2[k], st[k][1]);
                buf[(j * GI + iq * 3 + k) * F4 + fq] = o.f;
            }
        }
        fence_async();
        __syncthreads();

        if (tid == 0) {
            const int tbase = t_start + ot * RT;
            #pragma unroll
            for (int j = 0; j < RT; j++) {
                const char* gdst = gout_base
                    + (size_t)(tbase + j) * (NS * 1024) + i_off;
                bulk_store(gdst, &buf[j * GI * F4], ROW_BYTES);
            }
            bulk_commit();
        }
    }

    if (tid == 0) bulk_wait_all();
}

extern "C" void kernel_launch(void* const* d_in, const int* in_sizes, int n_in,
                              void* d_out, int out_size) {
    const float* inp = (const float*)d_in[0];
    float* out       = (float*)d_out;
    cudaFuncSetAttribute(laplace_kernel,
                         cudaFuncAttributeMaxDynamicSharedMemorySize, SMEM_BYTES);
    dim3 grid(NIB, NCHUNK);   // 9 x 16 = 144 blocks
    laplace_kernel<<<grid, THR, SMEM_BYTES>>>(inp, out);
}

// round 9
// speedup vs baseline: 1.2778x; 1.2778x over previous
#include <cuda_runtime.h>
#include <cuda_bf16.h>
#include <math.h>
#include <stdint.h>

// Laplace diagonal recurrence:
//   out[t, i, f] = e[i] * out[t-1, i, f] + decay[i] * inp[t, f]
// T = 2048, N_S = 108, F = 256, fp32.
//
// R9 = R5 (best, 72us) with ONE change: stores are st.global.wt
// (write-through, no dirty L2 lines to evict). Model: every prior variant
// pinned at the ~6300 B/cyc full-chip LTS cap, paid twice per output byte
// (allocate + eviction). Write-through pays it once.

constexpr int T_LEN  = 2048;
constexpr int F      = 256;
constexpr int NS     = 108;
constexpr int CHUNK  = 128;
constexpr int WARM   = 64;
constexpr int NCHUNK = T_LEN / CHUNK;   // 16
constexpr int GI     = 6;               // i-values per block
constexpr int NIB    = NS / GI;         // 18
constexpr int PF     = 8;               // prefetch depth (rows)
constexpr int F4     = F / 4;           // 64 float4 lanes per row

typedef unsigned long long u64;

__device__ __forceinline__ u64 fma2(u64 a, u64 b, u64 c) {
    u64 d;
    asm("fma.rn.f32x2 %0, %1, %2, %3;" : "=l"(d) : "l"(a), "l"(b), "l"(c));
    return d;
}
__device__ __forceinline__ u64 mul2(u64 a, u64 b) {
    u64 d;
    asm("mul.rn.f32x2 %0, %1, %2;" : "=l"(d) : "l"(a), "l"(b));
    return d;
}
__device__ __forceinline__ u64 pack2(float lo, float hi) {
    u64 d;
    asm("mov.b64 %0, {%1, %2};" : "=l"(d) : "f"(lo), "f"(hi));
    return d;
}
__device__ __forceinline__ void stwt4(float4* p, u64 lo, u64 hi) {
    asm volatile("st.global.wt.v4.b32 [%0], {%1, %2, %3, %4};"
                 :: "l"(p),
                    "r"((unsigned)(lo & 0xffffffffu)), "r"((unsigned)(lo >> 32)),
                    "r"((unsigned)(hi & 0xffffffffu)), "r"((unsigned)(hi >> 32))
                 : "memory");
}

union V4 {
    float4 f;
    u64    u[2];
};

__global__ __launch_bounds__(128)
void laplace_kernel(const float* __restrict__ inp, float* __restrict__ out) {
    const int tid = threadIdx.x;
    const int fq  = tid & 63;        // float4 lane: f = 4*fq
    const int iq  = tid >> 6;        // 0..1 -> which half of the 6 i's
    const int ib  = blockIdx.x;      // 0..17
    const int chunk = blockIdx.y;    // 0..15

    // Per-i constants in double precision (matches reference ~1e-7).
    u64 e2[3], d2[3];
    const double c = pow(20.0, 1.0 / 99.0) - 1.0;
    #pragma unroll
    for (int k = 0; k < 3; k++) {
        int i = ib * GI + iq * 3 + k;
        double tau = pow(1.0 + c, (double)(i - 4));
        double s   = 4.0 / tau;
        double ed  = exp(-s);
        float ef = (float)ed;
        float df = (float)((1.0 - ed) / s);
        e2[k] = pack2(ef, ef);
        d2[k] = pack2(df, df);
    }

    const int t_start = chunk * CHUNK;
    const int warm    = (t_start < WARM) ? t_start : WARM;  // 0 or 64
    const int t0      = t_start - warm;
    const int steps   = warm + CHUNK;                        // 128 or 192

    const float4* __restrict__ ip = reinterpret_cast<const float4*>(inp)
                                    + (size_t)t0 * F4 + fq;

    // Scaled states: st' = e*st' + x;  out = dcy * st'.
    u64 st[3][2];
    #pragma unroll
    for (int k = 0; k < 3; k++) { st[k][0] = 0ull; st[k][1] = 0ull; }

    // Prime the register pipeline.
    V4 pf[PF];
    #pragma unroll
    for (int j = 0; j < PF; j++) pf[j].f = __ldg(ip + j * F4);

    // ---- warm-up (no stores), warm is 0 or 64, divisible by PF ----
    for (int tb = 0; tb < warm; tb += PF) {
        #pragma unroll
        for (int j = 0; j < PF; j++) {
            const int t  = tb + j;
            const u64 x0 = pf[j].u[0];
            const u64 x1 = pf[j].u[1];
            const int tn = t + PF;
            if (tn < steps) pf[j].f = __ldg(ip + (size_t)tn * F4);
            #pragma unroll
            for (int k = 0; k < 3; k++) {
                st[k][0] = fma2(e2[k], st[k][0], x0);
                st[k][1] = fma2(e2[k], st[k][1], x1);
            }
        }
    }

    // ---- main: CHUNK=128 stored rows ----
    float4* op = reinterpret_cast<float4*>(out)
               + ((size_t)t_start * NS + (size_t)(ib * GI + iq * 3)) * F4 + fq;
    for (int tb = 0; tb < CHUNK; tb += PF) {
        #pragma unroll
        for (int j = 0; j < PF; j++) {
            const int t  = warm + tb + j;
            const u64 x0 = pf[j].u[0];
            const u64 x1 = pf[j].u[1];
            const int tn = t + PF;
            if (tn < steps) pf[j].f = __ldg(ip + (size_t)tn * F4);
            #pragma unroll
            for (int k = 0; k < 3; k++) {
                st[k][0] = fma2(e2[k], st[k][0], x0);
                st[k][1] = fma2(e2[k], st[k][1], x1);
                u64 o0 = mul2(d2[k], st[k][0]);
                u64 o1 = mul2(d2[k], st[k][1]);
                stwt4(op + k * F4, o0, o1);   // write-through STG.128
            }
            op += NS * F4;
        }
    }
}

extern "C" void kernel_launch(void* const* d_in, const int* in_sizes, int n_in,
                              void* d_out, int out_size) {
    const float* inp = (const float*)d_in[0];
    float* out       = (float*)d_out;
    dim3 grid(NIB, NCHUNK);   // 18 x 16 = 288 blocks
    laplace_kernel<<<grid, 128>>>(inp, out);
}

// round 10
// speedup vs baseline: 1.5271x; 1.1951x over previous
#include <cuda_runtime.h>
#include <cuda_bf16.h>
#include <math.h>
#include <stdint.h>

// Laplace diagonal recurrence:
//   out[t, i, f] = e[i] * out[t-1, i, f] + decay[i] * inp[t, f]
// T = 2048, N_S = 108, F = 256, fp32.
//
// R10: double per-warp-step payload. Evidence from R3/R4/R5/R7: time is
// proportional to TOTAL warp-steps (~348 SMSP-cyc each), independent of
// warp count / instruction count / load path. So: each thread now carries
// 6 i-states of float4 (24 elements per step, 6 STG.128/step). Block=128
// threads covers GI=12 i-values; grid = 9 x 16 = 144 blocks; total
// warp-steps halve vs R5. Same f32x2 math, PF=8 register prefetch,
// CHUNK=128/WARM=64, plain STG.128.

constexpr int T_LEN  = 2048;
constexpr int F      = 256;
constexpr int NS     = 108;
constexpr int CHUNK  = 128;
constexpr int WARM   = 64;
constexpr int NCHUNK = T_LEN / CHUNK;   // 16
constexpr int KI     = 6;               // i-states per thread
constexpr int GI     = 12;              // i-values per block (2 iq halves)
constexpr int NIB    = NS / GI;         // 9
constexpr int PF     = 8;               // prefetch depth (rows)
constexpr int F4     = F / 4;           // 64 float4 lanes per row

typedef unsigned long long u64;

__device__ __forceinline__ u64 fma2(u64 a, u64 b, u64 c) {
    u64 d;
    asm("fma.rn.f32x2 %0, %1, %2, %3;" : "=l"(d) : "l"(a), "l"(b), "l"(c));
    return d;
}
__device__ __forceinline__ u64 mul2(u64 a, u64 b) {
    u64 d;
    asm("mul.rn.f32x2 %0, %1, %2;" : "=l"(d) : "l"(a), "l"(b));
    return d;
}
__device__ __forceinline__ u64 pack2(float lo, float hi) {
    u64 d;
    asm("mov.b64 %0, {%1, %2};" : "=l"(d) : "f"(lo), "f"(hi));
    return d;
}

union V4 {
    float4 f;
    u64    u[2];
};

__global__ __launch_bounds__(128, 1)
void laplace_kernel(const float* __restrict__ inp, float* __restrict__ out) {
    const int tid = threadIdx.x;
    const int fq  = tid & 63;        // float4 lane: f = 4*fq
    const int iq  = tid >> 6;        // 0..1 -> which half of the 12 i's
    const int ib  = blockIdx.x;      // 0..8
    const int chunk = blockIdx.y;    // 0..15

    // Per-i constants in double precision (matches reference ~1e-7).
    u64 e2[KI], d2[KI];
    const double c = pow(20.0, 1.0 / 99.0) - 1.0;
    #pragma unroll
    for (int k = 0; k < KI; k++) {
        int i = ib * GI + iq * KI + k;
        double tau = pow(1.0 + c, (double)(i - 4));
        double s   = 4.0 / tau;
        double ed  = exp(-s);
        float ef = (float)ed;
        float df = (float)((1.0 - ed) / s);
        e2[k] = pack2(ef, ef);
        d2[k] = pack2(df, df);
    }

    const int t_start = chunk * CHUNK;
    const int warm    = (t_start < WARM) ? t_start : WARM;  // 0 or 64
    const int t0      = t_start - warm;
    const int steps   = warm + CHUNK;                        // 128 or 192

    const float4* __restrict__ ip = reinterpret_cast<const float4*>(inp)
                                    + (size_t)t0 * F4 + fq;

    // Scaled states: st' = e*st' + x;  out = dcy * st'.
    u64 st[KI][2];
    #pragma unroll
    for (int k = 0; k < KI; k++) { st[k][0] = 0ull; st[k][1] = 0ull; }

    // Prime the register pipeline.
    V4 pf[PF];
    #pragma unroll
    for (int j = 0; j < PF; j++) pf[j].f = __ldg(ip + j * F4);

    // ---- warm-up (no stores), warm is 0 or 64, divisible by PF ----
    for (int tb = 0; tb < warm; tb += PF) {
        #pragma unroll
        for (int j = 0; j < PF; j++) {
            const int t  = tb + j;
            const u64 x0 = pf[j].u[0];
            const u64 x1 = pf[j].u[1];
            const int tn = t + PF;
            if (tn < steps) pf[j].f = __ldg(ip + (size_t)tn * F4);
            #pragma unroll
            for (int k = 0; k < KI; k++) {
                st[k][0] = fma2(e2[k], st[k][0], x0);
                st[k][1] = fma2(e2[k], st[k][1], x1);
            }
        }
    }

    // ---- main: CHUNK=128 stored rows, 6 STG.128 per thread per row ----
    float4* op = reinterpret_cast<float4*>(out)
               + ((size_t)t_start * NS + (size_t)(ib * GI + iq * KI)) * F4 + fq;
    for (int tb = 0; tb < CHUNK; tb += PF) {
        #pragma unroll
        for (int j = 0; j < PF; j++) {
            const int t  = warm + tb + j;
            const u64 x0 = pf[j].u[0];
            const u64 x1 = pf[j].u[1];
            const int tn = t + PF;
            if (tn < steps) pf[j].f = __ldg(ip + (size_t)tn * F4);
            #pragma unroll
            for (int k = 0; k < KI; k++) {
                st[k][0] = fma2(e2[k], st[k][0], x0);
                st[k][1] = fma2(e2[k], st[k][1], x1);
                V4 o;
                o.u[0] = mul2(d2[k], st[k][0]);
                o.u[1] = mul2(d2[k], st[k][1]);
                op[k * F4] = o.f;   // immediate offsets 0..5120B
            }
            op += NS * F4;
        }
    }
}

extern "C" void kernel_launch(void* const* d_in, const int* in_sizes, int n_in,
                              void* d_out, int out_size) {
    const float* inp = (const float*)d_in[0];
    float* out       = (float*)d_out;
    dim3 grid(NIB, NCHUNK);   // 9 x 16 = 144 blocks
    laplace_kernel<<<grid, 128>>>(inp, out);
}